// round 5
// baseline (speedup 1.0000x reference)
#include <cuda_runtime.h>
#include <cuda_bf16.h>
#include <cstdint>

#define NN 50000
#define EE 1600000
#define FF 128
#define HH 256

// ---------------- static device scratch (allocation-free rule) ----------------
__device__ __align__(16) float g_bufA[(size_t)NN * HH];
__device__ __align__(16) float g_bufB[(size_t)NN * HH];
__device__ __align__(16) float g_bufC[(size_t)NN * HH];
__device__ float g_dinv[NN];       // deg accumulator, then rsqrt in place
__device__ int   g_cnt[NN];
__device__ int   g_fill[NN];
__device__ int   g_rowptr[NN + 1];
__device__ int   g_col[EE];
__device__ float g_val[EE];
__device__ float g_acc[2];
__device__ int   g_not64;          // 1 if edges are NOT int64 (i.e. int32)

// device-side buffer selector (no host-side symbol queries)
__device__ __forceinline__ float* BUF(int s) {
    return s == 0 ? g_bufA : (s == 1 ? g_bufB : g_bufC);
}

// edge index fetch, width decided by detection flag
__device__ __forceinline__ int edge_at(const void* edges, size_t idx) {
    if (g_not64) return ((const int*)edges)[idx];
    long long v = ((const long long*)edges)[idx];
    return (int)v;
}

// ---------------- setup kernels (rebuilt every launch; deterministic work) ----
__global__ __launch_bounds__(256) void init_kernel() {
    int i = blockIdx.x * blockDim.x + threadIdx.x;
    if (i < NN) { g_dinv[i] = 1.0f; g_cnt[i] = 0; g_fill[i] = 0; }
    if (i == 0) { g_acc[0] = 0.f; g_acc[1] = 0.f; g_not64 = 0; }
}

// scan EE int64 slots == 2*EE int32 slots == exactly the buffer size if int32.
__global__ __launch_bounds__(256) void detect_kernel(const void* edges) {
    int i = blockIdx.x * blockDim.x + threadIdx.x;
    if (i >= EE) return;
    long long v = ((const long long*)edges)[i];
    if (v < 0 || v >= NN) atomicOr(&g_not64, 1);
}

__global__ __launch_bounds__(256) void edge_count_kernel(
    const void* __restrict__ edges, const float* __restrict__ w) {
    int e = blockIdx.x * blockDim.x + threadIdx.x;
    if (e >= EE) return;
    int dst = edge_at(edges, (size_t)EE + e);
    if ((unsigned)dst >= NN) return;
    atomicAdd(&g_dinv[dst], w[e]);
    atomicAdd(&g_cnt[dst], 1);
}

__global__ __launch_bounds__(256) void rsqrt_kernel() {
    int i = blockIdx.x * blockDim.x + threadIdx.x;
    if (i < NN) g_dinv[i] = rsqrtf(g_dinv[i]);   // deg >= 1 (self loop) always
}

// single-block exclusive scan over g_cnt -> g_rowptr (N=50000, 1024 threads)
__global__ __launch_bounds__(1024) void scan_kernel() {
    __shared__ int sh[1024];
    const int CH = (NN + 1023) / 1024;          // 49
    int t = threadIdx.x;
    int base = t * CH;
    int s = 0;
    for (int i = 0; i < CH; i++) {
        int idx = base + i;
        if (idx < NN) s += g_cnt[idx];
    }
    sh[t] = s;
    __syncthreads();
    for (int off = 1; off < 1024; off <<= 1) {
        int v = sh[t];
        int add = (t >= off) ? sh[t - off] : 0;
        __syncthreads();
        sh[t] = v + add;
        __syncthreads();
    }
    int run = (t == 0) ? 0 : sh[t - 1];
    for (int i = 0; i < CH; i++) {
        int idx = base + i;
        if (idx < NN) { g_rowptr[idx] = run; run += g_cnt[idx]; }
    }
    if (t == 1023) g_rowptr[NN] = run;
}

__global__ __launch_bounds__(256) void fill_kernel(
    const void* __restrict__ edges, const float* __restrict__ w) {
    int e = blockIdx.x * blockDim.x + threadIdx.x;
    if (e >= EE) return;
    int src = edge_at(edges, e);
    int dst = edge_at(edges, (size_t)EE + e);
    if ((unsigned)src >= NN || (unsigned)dst >= NN) return;
    int pos = g_rowptr[dst] + atomicAdd(&g_fill[dst], 1);
    if ((unsigned)pos >= EE) return;
    g_col[pos] = src;
    g_val[pos] = g_dinv[src] * w[e] * g_dinv[dst];
}

// ---------------- SpMM: y = S x  (CSR gather-sum, no atomics) ----------------
template <int C>
__global__ __launch_bounds__(C) void spmm_kernel(
    const float* __restrict__ ext, int in_sel, int out_sel) {
    const float* __restrict__ x = (in_sel < 0) ? ext : BUF(in_sel);
    float* __restrict__ y = BUF(out_sel);
    int n = blockIdx.x;
    int f = threadIdx.x;
    int s = g_rowptr[n], e = g_rowptr[n + 1];
    float d = g_dinv[n];
    float s0 = d * d * x[(size_t)n * C + f];     // self loop term
    float s1 = 0.f, s2 = 0.f, s3 = 0.f;
    __shared__ int   scol[128];
    __shared__ float sval[128];
    for (int base = s; base < e; base += 128) {
        int m = min(128, e - base);
        __syncthreads();
        if (f < 128 && f < m) {
            scol[f] = g_col[base + f];
            sval[f] = g_val[base + f];
        }
        __syncthreads();
        int j = 0;
        for (; j + 4 <= m; j += 4) {
            s0 += sval[j + 0] * x[(size_t)scol[j + 0] * C + f];
            s1 += sval[j + 1] * x[(size_t)scol[j + 1] * C + f];
            s2 += sval[j + 2] * x[(size_t)scol[j + 2] * C + f];
            s3 += sval[j + 3] * x[(size_t)scol[j + 3] * C + f];
        }
        for (; j < m; j++) s0 += sval[j] * x[(size_t)scol[j] * C + f];
    }
    y[(size_t)n * C + f] = (s0 + s1) + (s2 + s3);
}

// ---------------- GEMM: C[M,256] = A[M,K] @ B[K,256] + bias ------------------
// 128x128 tile, BK=8, 256 threads, 8x8 per thread, plain fp32 FMA.
__global__ __launch_bounds__(256) void gemm_bias_kernel(
    int in_sel, const float* __restrict__ B,
    const float* __restrict__ bias, int out_sel, int M, int K) {
    const float* __restrict__ A = BUF(in_sel);
    float* __restrict__ C = BUF(out_sel);
    __shared__ alignas(16) float As[8][128];
    __shared__ alignas(16) float Bs[8][128];

    int t  = threadIdx.x;
    int tx = t & 15, ty = t >> 4;                 // 16 x 16 thread grid
    int row0 = blockIdx.y * 128;
    int col0 = blockIdx.x * 128;
    int a_r = t >> 1, a_c = (t & 1) * 4;
    int b_r = t >> 5, b_c = (t & 31) * 4;

    float acc[8][8];
#pragma unroll
    for (int i = 0; i < 8; i++)
#pragma unroll
        for (int j = 0; j < 8; j++) acc[i][j] = 0.f;

    bool arow_ok = (row0 + a_r) < M;
    const float* Aptr = A + (size_t)(row0 + a_r) * K + a_c;

    for (int k0 = 0; k0 < K; k0 += 8) {
        float4 av = make_float4(0.f, 0.f, 0.f, 0.f);
        if (arow_ok) av = *(const float4*)(Aptr + k0);
        As[a_c + 0][a_r] = av.x;
        As[a_c + 1][a_r] = av.y;
        As[a_c + 2][a_r] = av.z;
        As[a_c + 3][a_r] = av.w;
        float4 bv = *(const float4*)(B + (size_t)(k0 + b_r) * HH + col0 + b_c);
        *(float4*)&Bs[b_r][b_c] = bv;
        __syncthreads();
#pragma unroll
        for (int kk = 0; kk < 8; kk++) {
            float ar[8], br[8];
            float4 a0 = *(const float4*)&As[kk][ty * 8];
            float4 a1 = *(const float4*)&As[kk][ty * 8 + 4];
            ar[0] = a0.x; ar[1] = a0.y; ar[2] = a0.z; ar[3] = a0.w;
            ar[4] = a1.x; ar[5] = a1.y; ar[6] = a1.z; ar[7] = a1.w;
            float4 b0 = *(const float4*)&Bs[kk][tx * 4];
            float4 b1 = *(const float4*)&Bs[kk][64 + tx * 4];
            br[0] = b0.x; br[1] = b0.y; br[2] = b0.z; br[3] = b0.w;
            br[4] = b1.x; br[5] = b1.y; br[6] = b1.z; br[7] = b1.w;
#pragma unroll
            for (int i = 0; i < 8; i++)
#pragma unroll
                for (int j = 0; j < 8; j++)
                    acc[i][j] = fmaf(ar[i], br[j], acc[i][j]);
        }
        __syncthreads();
    }

    float ba[8];
#pragma unroll
    for (int j = 0; j < 4; j++) {
        ba[j]     = bias[col0 + tx * 4 + j];
        ba[4 + j] = bias[col0 + 64 + tx * 4 + j];
    }
#pragma unroll
    for (int i = 0; i < 8; i++) {
        int gr = row0 + ty * 8 + i;
        if (gr >= M) continue;
        float4 o;
        o.x = acc[i][0] + ba[0]; o.y = acc[i][1] + ba[1];
        o.z = acc[i][2] + ba[2]; o.w = acc[i][3] + ba[3];
        *(float4*)(C + (size_t)gr * HH + col0 + tx * 4) = o;
        o.x = acc[i][4] + ba[4]; o.y = acc[i][5] + ba[5];
        o.z = acc[i][6] + ba[6]; o.w = acc[i][7] + ba[7];
        *(float4*)(C + (size_t)gr * HH + col0 + 64 + tx * 4) = o;
    }
}

// ---------------- fused LayerNorm + residual + ReLU ---------------------------
__global__ __launch_bounds__(HH) void ln_relu_kernel(
    int t_sel, int res_sel,
    const float* __restrict__ g, const float* __restrict__ b, int out_sel) {
    const float* __restrict__ t_in = BUF(t_sel);
    const float* __restrict__ res  = BUF(res_sel);
    float* __restrict__ out        = BUF(out_sel);
    int n = blockIdx.x;
    int f = threadIdx.x;
    size_t idx = (size_t)n * HH + f;
    float v = t_in[idx];
    float s = v, q = v * v;
#pragma unroll
    for (int o = 16; o; o >>= 1) {
        s += __shfl_down_sync(0xFFFFFFFFu, s, o);
        q += __shfl_down_sync(0xFFFFFFFFu, q, o);
    }
    __shared__ float ss[8], sq[8];
    int w = f >> 5, l = f & 31;
    if (l == 0) { ss[w] = s; sq[w] = q; }
    __syncthreads();
    if (f == 0) {
        float S = 0.f, Q = 0.f;
#pragma unroll
        for (int i = 0; i < 8; i++) { S += ss[i]; Q += sq[i]; }
        ss[0] = S; sq[0] = Q;
    }
    __syncthreads();
    float mu  = ss[0] * (1.0f / HH);
    float var = sq[0] * (1.0f / HH) - mu * mu;
    var = fmaxf(var, 0.f);
    float rs = rsqrtf(var + 1e-5f);
    float y = (v - mu) * rs * g[f] + b[f] + res[idx];
    out[idx] = fmaxf(y, 0.f);
}

// ---------------- global mean pool of x @ fc_W --------------------------------
__global__ __launch_bounds__(256) void pool_kernel(int in_sel,
                                                   const float* __restrict__ fcW) {
    const float* __restrict__ x = BUF(in_sel);
    __shared__ float w0s[HH], w1s[HH];
    int t = threadIdx.x;
    w0s[t] = fcW[2 * t];
    w1s[t] = fcW[2 * t + 1];
    __syncthreads();
    int lane = t & 31, warp = t >> 5;
    int gw = blockIdx.x * 8 + warp;
    int nw = gridDim.x * 8;
    float a0 = 0.f, a1 = 0.f;
    for (int n = gw; n < NN; n += nw) {
        size_t base = (size_t)n * HH;
#pragma unroll
        for (int j = 0; j < 8; j++) {
            float v = x[base + lane + 32 * j];
            a0 += v * w0s[lane + 32 * j];
            a1 += v * w1s[lane + 32 * j];
        }
    }
#pragma unroll
    for (int o = 16; o; o >>= 1) {
        a0 += __shfl_down_sync(0xFFFFFFFFu, a0, o);
        a1 += __shfl_down_sync(0xFFFFFFFFu, a1, o);
    }
    if (lane == 0) {
        atomicAdd(&g_acc[0], a0);
        atomicAdd(&g_acc[1], a1);
    }
}

__global__ __launch_bounds__(32) void finish_kernel(const float* __restrict__ fcb,
                                                    float* __restrict__ out) {
    if (threadIdx.x == 0) {
        out[0] = g_acc[0] * (1.0f / NN) + fcb[0];
        out[1] = g_acc[1] * (1.0f / NN) + fcb[1];
    }
}

// ---------------- launch ------------------------------------------------------
extern "C" void kernel_launch(void* const* d_in, const int* in_sizes, int n_in,
                              void* d_out, int out_size) {
    const float* node  = (const float*)d_in[0];
    const void*  edges = d_in[1];
    const float* eattr = (const float*)d_in[2];
    const float* W1    = (const float*)d_in[3];
    const float* b1    = (const float*)d_in[4];
    const float* Wc    = (const float*)d_in[5];
    const float* bc    = (const float*)d_in[6];
    const float* lng   = (const float*)d_in[7];
    const float* lnb   = (const float*)d_in[8];
    const float* fcW   = (const float*)d_in[9];
    const float* fcb   = (const float*)d_in[10];
    float* out = (float*)d_out;

    const int TB = 256;
    init_kernel<<<(NN + TB - 1) / TB, TB>>>();
    detect_kernel<<<(EE + TB - 1) / TB, TB>>>(edges);
    edge_count_kernel<<<(EE + TB - 1) / TB, TB>>>(edges, eattr);
    rsqrt_kernel<<<(NN + TB - 1) / TB, TB>>>();
    scan_kernel<<<1, 1024>>>();
    fill_kernel<<<(EE + TB - 1) / TB, TB>>>(edges, eattr);

    dim3 ggrid(2, (NN + 127) / 128);

    // layer 1: aggregate first (F=128 is cheaper), then GEMM:  x0 = (S·node)·W1 + b1
    spmm_kernel<FF><<<NN, FF>>>(node, -1, 1);
    gemm_bias_kernel<<<ggrid, 256>>>(1, W1, b1, 0, NN, FF);

    // i=0: x in buf0 -> spmm buf1 -> gemm buf2 -> ln(buf2, res buf0) -> buf1
    spmm_kernel<HH><<<NN, HH>>>(nullptr, 0, 1);
    gemm_bias_kernel<<<ggrid, 256>>>(1, Wc + 0 * HH * HH, bc + 0 * HH, 2, NN, HH);
    ln_relu_kernel<<<NN, HH>>>(2, 0, lng + 0 * HH, lnb + 0 * HH, 1);

    // i=1
    spmm_kernel<HH><<<NN, HH>>>(nullptr, 1, 0);
    gemm_bias_kernel<<<ggrid, 256>>>(0, Wc + 1 * HH * HH, bc + 1 * HH, 2, NN, HH);
    ln_relu_kernel<<<NN, HH>>>(2, 1, lng + 1 * HH, lnb + 1 * HH, 0);

    // i=2
    spmm_kernel<HH><<<NN, HH>>>(nullptr, 0, 1);
    gemm_bias_kernel<<<ggrid, 256>>>(1, Wc + 2 * HH * HH, bc + 2 * HH, 2, NN, HH);
    ln_relu_kernel<<<NN, HH>>>(2, 0, lng + 2 * HH, lnb + 2 * HH, 1);

    pool_kernel<<<256, 256>>>(1, fcW);
    finish_kernel<<<1, 32>>>(fcb, out);
}

// round 6
// speedup vs baseline: 1.1478x; 1.1478x over previous
#include <cuda_runtime.h>
#include <cuda_bf16.h>
#include <cstdint>

#define NN 50000
#define EE 1600000
#define FF 128
#define HH 256

// ---------------- static device scratch (allocation-free rule) ----------------
__device__ __align__(16) float g_bufA[(size_t)NN * HH];
__device__ __align__(16) float g_bufB[(size_t)NN * HH];
__device__ __align__(16) float g_bufC[(size_t)NN * HH];
__device__ __align__(16) __nv_bfloat16 g_h[(size_t)NN * HH];  // bf16 mirror for gathers
__device__ float g_dinv[NN];
__device__ int   g_cnt[NN];
__device__ int   g_fill[NN];
__device__ int   g_rowptr[NN + 1];
__device__ int   g_col[EE];
__device__ float g_val[EE];
__device__ float g_acc[2];
__device__ int   g_not64;

__device__ __forceinline__ float* BUF(int s) {
    return s == 0 ? g_bufA : (s == 1 ? g_bufB : g_bufC);
}

__device__ __forceinline__ int edge_at(const void* edges, size_t idx) {
    if (g_not64) return ((const int*)edges)[idx];
    long long v = ((const long long*)edges)[idx];
    return (int)v;
}

// ---- packed f32x2 helpers: REGISTER-ONLY packing (no memory type-punning) ----
__device__ __forceinline__ unsigned long long pk2(float lo, float hi) {
    unsigned long long d;
    asm("mov.b64 %0, {%1, %2};" : "=l"(d) : "f"(lo), "f"(hi));
    return d;
}
__device__ __forceinline__ unsigned long long fma2(unsigned long long a,
                                                   unsigned long long b,
                                                   unsigned long long c) {
    unsigned long long d;
    asm("fma.rn.f32x2 %0, %1, %2, %3;" : "=l"(d) : "l"(a), "l"(b), "l"(c));
    return d;
}
__device__ __forceinline__ void upk2(unsigned long long v, float& lo, float& hi) {
    asm("mov.b64 {%0, %1}, %2;" : "=f"(lo), "=f"(hi) : "l"(v));
}

// ---------------- setup kernels ----------------------------------------------
__global__ __launch_bounds__(256) void init_kernel() {
    int i = blockIdx.x * blockDim.x + threadIdx.x;
    if (i < NN) { g_dinv[i] = 1.0f; g_cnt[i] = 0; g_fill[i] = 0; }
    if (i == 0) { g_acc[0] = 0.f; g_acc[1] = 0.f; g_not64 = 0; }
}

__global__ __launch_bounds__(256) void detect_kernel(const void* edges) {
    int i = blockIdx.x * blockDim.x + threadIdx.x;
    if (i >= EE) return;
    long long v = ((const long long*)edges)[i];
    if (v < 0 || v >= NN) atomicOr(&g_not64, 1);
}

__global__ __launch_bounds__(256) void edge_count_kernel(
    const void* __restrict__ edges, const float* __restrict__ w) {
    int e = blockIdx.x * blockDim.x + threadIdx.x;
    if (e >= EE) return;
    int dst = edge_at(edges, (size_t)EE + e);
    if ((unsigned)dst >= NN) return;
    atomicAdd(&g_dinv[dst], w[e]);
    atomicAdd(&g_cnt[dst], 1);
}

__global__ __launch_bounds__(256) void rsqrt_kernel() {
    int i = blockIdx.x * blockDim.x + threadIdx.x;
    if (i < NN) g_dinv[i] = rsqrtf(g_dinv[i]);
}

__global__ __launch_bounds__(1024) void scan_kernel() {
    __shared__ int sh[1024];
    const int CH = (NN + 1023) / 1024;
    int t = threadIdx.x;
    int base = t * CH;
    int s = 0;
    for (int i = 0; i < CH; i++) {
        int idx = base + i;
        if (idx < NN) s += g_cnt[idx];
    }
    sh[t] = s;
    __syncthreads();
    for (int off = 1; off < 1024; off <<= 1) {
        int v = sh[t];
        int add = (t >= off) ? sh[t - off] : 0;
        __syncthreads();
        sh[t] = v + add;
        __syncthreads();
    }
    int run = (t == 0) ? 0 : sh[t - 1];
    for (int i = 0; i < CH; i++) {
        int idx = base + i;
        if (idx < NN) { g_rowptr[idx] = run; run += g_cnt[idx]; }
    }
    if (t == 1023) g_rowptr[NN] = run;
}

__global__ __launch_bounds__(256) void fill_kernel(
    const void* __restrict__ edges, const float* __restrict__ w) {
    int e = blockIdx.x * blockDim.x + threadIdx.x;
    if (e >= EE) return;
    int src = edge_at(edges, e);
    int dst = edge_at(edges, (size_t)EE + e);
    if ((unsigned)src >= NN || (unsigned)dst >= NN) return;
    int pos = g_rowptr[dst] + atomicAdd(&g_fill[dst], 1);
    if ((unsigned)pos >= EE) return;
    g_col[pos] = src;
    g_val[pos] = g_dinv[src] * w[e] * g_dinv[dst];
}

// convert external node features (fp32) -> bf16 mirror
__global__ __launch_bounds__(256) void cvt_node_kernel(const float* __restrict__ node) {
    int i = blockIdx.x * blockDim.x + threadIdx.x;
    if (i < NN * FF) g_h[i] = __float2bfloat16(node[i]);
}

// ---------------- SpMM: y = S x, bf16 gathers, fp32 accumulate ---------------
// P = feature pairs per row (C/2). One block per node, P threads.
template <int P>
__global__ __launch_bounds__(P) void spmm_h_kernel(int out_sel) {
    float* __restrict__ y = BUF(out_sel);
    const __nv_bfloat162* __restrict__ x = (const __nv_bfloat162*)g_h;
    int n = blockIdx.x;
    int f = threadIdx.x;
    int s = g_rowptr[n], e = g_rowptr[n + 1];
    float d = g_dinv[n];
    float2 xs = __bfloat1622float2(x[(size_t)n * P + f]);
    float ax0 = d * d * xs.x, ay0 = d * d * xs.y;   // self-loop term
    float ax1 = 0.f, ay1 = 0.f, ax2 = 0.f, ay2 = 0.f, ax3 = 0.f, ay3 = 0.f;
    __shared__ int   scol[P];
    __shared__ float sval[P];
    for (int base = s; base < e; base += P) {
        int m = min(P, e - base);
        __syncthreads();
        if (f < m) {
            scol[f] = g_col[base + f];
            sval[f] = g_val[base + f];
        }
        __syncthreads();
        int j = 0;
        for (; j + 4 <= m; j += 4) {
            float2 v0 = __bfloat1622float2(x[(size_t)scol[j + 0] * P + f]);
            float2 v1 = __bfloat1622float2(x[(size_t)scol[j + 1] * P + f]);
            float2 v2 = __bfloat1622float2(x[(size_t)scol[j + 2] * P + f]);
            float2 v3 = __bfloat1622float2(x[(size_t)scol[j + 3] * P + f]);
            ax0 = fmaf(sval[j + 0], v0.x, ax0); ay0 = fmaf(sval[j + 0], v0.y, ay0);
            ax1 = fmaf(sval[j + 1], v1.x, ax1); ay1 = fmaf(sval[j + 1], v1.y, ay1);
            ax2 = fmaf(sval[j + 2], v2.x, ax2); ay2 = fmaf(sval[j + 2], v2.y, ay2);
            ax3 = fmaf(sval[j + 3], v3.x, ax3); ay3 = fmaf(sval[j + 3], v3.y, ay3);
        }
        for (; j < m; j++) {
            float2 v = __bfloat1622float2(x[(size_t)scol[j] * P + f]);
            ax0 = fmaf(sval[j], v.x, ax0); ay0 = fmaf(sval[j], v.y, ay0);
        }
    }
    float2 o;
    o.x = (ax0 + ax1) + (ax2 + ax3);
    o.y = (ay0 + ay1) + (ay2 + ay3);
    *(float2*)(y + (size_t)n * (2 * P) + 2 * f) = o;
}

// ---------------- GEMM: C[M,256] = A[M,K] @ B[K,256] + bias (FFMA2) ----------
// 128x128 tile, BK=8, 256 threads, 8x8 per thread via packed f32x2.
// If write_h != 0, also writes bf16 mirror of C into g_h.
__global__ __launch_bounds__(256) void gemm_bias_kernel(
    int in_sel, const float* __restrict__ B,
    const float* __restrict__ bias, int out_sel, int M, int K, int write_h) {
    const float* __restrict__ A = BUF(in_sel);
    float* __restrict__ C = BUF(out_sel);
    __shared__ alignas(16) float As[8][128];
    __shared__ alignas(16) float Bs[8][128];

    int t  = threadIdx.x;
    int tx = t & 15, ty = t >> 4;
    int row0 = blockIdx.y * 128;
    int col0 = blockIdx.x * 128;
    int a_r = t >> 1, a_c = (t & 1) * 4;
    int b_r = t >> 5, b_c = (t & 31) * 4;

    unsigned long long acc2[8][4];
#pragma unroll
    for (int i = 0; i < 8; i++)
#pragma unroll
        for (int j = 0; j < 4; j++) acc2[i][j] = 0ull;

    bool arow_ok = (row0 + a_r) < M;
    const float* Aptr = A + (size_t)(row0 + a_r) * K + a_c;

    for (int k0 = 0; k0 < K; k0 += 8) {
        float4 av = make_float4(0.f, 0.f, 0.f, 0.f);
        if (arow_ok) av = *(const float4*)(Aptr + k0);
        As[a_c + 0][a_r] = av.x;
        As[a_c + 1][a_r] = av.y;
        As[a_c + 2][a_r] = av.z;
        As[a_c + 3][a_r] = av.w;
        float4 bv = *(const float4*)(B + (size_t)(k0 + b_r) * HH + col0 + b_c);
        *(float4*)&Bs[b_r][b_c] = bv;
        __syncthreads();
#pragma unroll
        for (int kk = 0; kk < 8; kk++) {
            float4 a0 = *(const float4*)&As[kk][ty * 8];
            float4 a1 = *(const float4*)&As[kk][ty * 8 + 4];
            float4 b0 = *(const float4*)&Bs[kk][tx * 4];
            float4 b1 = *(const float4*)&Bs[kk][64 + tx * 4];
            unsigned long long a2[8];
            a2[0] = pk2(a0.x, a0.x); a2[1] = pk2(a0.y, a0.y);
            a2[2] = pk2(a0.z, a0.z); a2[3] = pk2(a0.w, a0.w);
            a2[4] = pk2(a1.x, a1.x); a2[5] = pk2(a1.y, a1.y);
            a2[6] = pk2(a1.z, a1.z); a2[7] = pk2(a1.w, a1.w);
            unsigned long long b2[4];
            b2[0] = pk2(b0.x, b0.y); b2[1] = pk2(b0.z, b0.w);
            b2[2] = pk2(b1.x, b1.y); b2[3] = pk2(b1.z, b1.w);
#pragma unroll
            for (int i = 0; i < 8; i++)
#pragma unroll
                for (int j = 0; j < 4; j++)
                    acc2[i][j] = fma2(a2[i], b2[j], acc2[i][j]);
        }
        __syncthreads();
    }

    float ba[8];
#pragma unroll
    for (int j = 0; j < 4; j++) {
        ba[j]     = bias[col0 + tx * 4 + j];
        ba[4 + j] = bias[col0 + 64 + tx * 4 + j];
    }
#pragma unroll
    for (int i = 0; i < 8; i++) {
        int gr = row0 + ty * 8 + i;
        if (gr >= M) continue;
        float lo, hi;
        float4 o0, o1;
        upk2(acc2[i][0], lo, hi); o0.x = lo + ba[0]; o0.y = hi + ba[1];
        upk2(acc2[i][1], lo, hi); o0.z = lo + ba[2]; o0.w = hi + ba[3];
        upk2(acc2[i][2], lo, hi); o1.x = lo + ba[4]; o1.y = hi + ba[5];
        upk2(acc2[i][3], lo, hi); o1.z = lo + ba[6]; o1.w = hi + ba[7];
        *(float4*)(C + (size_t)gr * HH + col0 + tx * 4) = o0;
        *(float4*)(C + (size_t)gr * HH + col0 + 64 + tx * 4) = o1;
        if (write_h) {
            __nv_bfloat162* hp = (__nv_bfloat162*)(g_h + (size_t)gr * HH);
            hp[(col0 + tx * 4) / 2]      = __float22bfloat162_rn(make_float2(o0.x, o0.y));
            hp[(col0 + tx * 4) / 2 + 1]  = __float22bfloat162_rn(make_float2(o0.z, o0.w));
            hp[(col0 + 64 + tx * 4) / 2]     = __float22bfloat162_rn(make_float2(o1.x, o1.y));
            hp[(col0 + 64 + tx * 4) / 2 + 1] = __float22bfloat162_rn(make_float2(o1.z, o1.w));
        }
    }
}

// ---------------- fused LayerNorm + residual + ReLU (+ bf16 mirror) ----------
__global__ __launch_bounds__(HH) void ln_relu_kernel(
    int t_sel, int res_sel,
    const float* __restrict__ g, const float* __restrict__ b, int out_sel) {
    const float* __restrict__ t_in = BUF(t_sel);
    const float* __restrict__ res  = BUF(res_sel);
    float* __restrict__ out        = BUF(out_sel);
    int n = blockIdx.x;
    int f = threadIdx.x;
    size_t idx = (size_t)n * HH + f;
    float v = t_in[idx];
    float s = v, q = v * v;
#pragma unroll
    for (int o = 16; o; o >>= 1) {
        s += __shfl_down_sync(0xFFFFFFFFu, s, o);
        q += __shfl_down_sync(0xFFFFFFFFu, q, o);
    }
    __shared__ float ss[8], sq[8];
    int w = f >> 5, l = f & 31;
    if (l == 0) { ss[w] = s; sq[w] = q; }
    __syncthreads();
    if (f == 0) {
        float S = 0.f, Q = 0.f;
#pragma unroll
        for (int i = 0; i < 8; i++) { S += ss[i]; Q += sq[i]; }
        ss[0] = S; sq[0] = Q;
    }
    __syncthreads();
    float mu  = ss[0] * (1.0f / HH);
    float var = sq[0] * (1.0f / HH) - mu * mu;
    var = fmaxf(var, 0.f);
    float rs = rsqrtf(var + 1e-5f);
    float y = (v - mu) * rs * g[f] + b[f] + res[idx];
    y = fmaxf(y, 0.f);
    out[idx] = y;
    g_h[idx] = __float2bfloat16(y);
}

// ---------------- global mean pool of x @ fc_W --------------------------------
__global__ __launch_bounds__(256) void pool_kernel(int in_sel,
                                                   const float* __restrict__ fcW) {
    const float* __restrict__ x = BUF(in_sel);
    __shared__ float w0s[HH], w1s[HH];
    int t = threadIdx.x;
    w0s[t] = fcW[2 * t];
    w1s[t] = fcW[2 * t + 1];
    __syncthreads();
    int lane = t & 31, warp = t >> 5;
    int gw = blockIdx.x * 8 + warp;
    int nw = gridDim.x * 8;
    float a0 = 0.f, a1 = 0.f;
    for (int n = gw; n < NN; n += nw) {
        size_t base = (size_t)n * HH;
#pragma unroll
        for (int j = 0; j < 8; j++) {
            float v = x[base + lane + 32 * j];
            a0 += v * w0s[lane + 32 * j];
            a1 += v * w1s[lane + 32 * j];
        }
    }
#pragma unroll
    for (int o = 16; o; o >>= 1) {
        a0 += __shfl_down_sync(0xFFFFFFFFu, a0, o);
        a1 += __shfl_down_sync(0xFFFFFFFFu, a1, o);
    }
    if (lane == 0) {
        atomicAdd(&g_acc[0], a0);
        atomicAdd(&g_acc[1], a1);
    }
}

__global__ __launch_bounds__(32) void finish_kernel(const float* __restrict__ fcb,
                                                    float* __restrict__ out) {
    if (threadIdx.x == 0) {
        out[0] = g_acc[0] * (1.0f / NN) + fcb[0];
        out[1] = g_acc[1] * (1.0f / NN) + fcb[1];
    }
}

// ---------------- launch ------------------------------------------------------
extern "C" void kernel_launch(void* const* d_in, const int* in_sizes, int n_in,
                              void* d_out, int out_size) {
    const float* node  = (const float*)d_in[0];
    const void*  edges = d_in[1];
    const float* eattr = (const float*)d_in[2];
    const float* W1    = (const float*)d_in[3];
    const float* b1    = (const float*)d_in[4];
    const float* Wc    = (const float*)d_in[5];
    const float* bc    = (const float*)d_in[6];
    const float* lng   = (const float*)d_in[7];
    const float* lnb   = (const float*)d_in[8];
    const float* fcW   = (const float*)d_in[9];
    const float* fcb   = (const float*)d_in[10];
    float* out = (float*)d_out;

    const int TB = 256;
    init_kernel<<<(NN + TB - 1) / TB, TB>>>();
    detect_kernel<<<(EE + TB - 1) / TB, TB>>>(edges);
    edge_count_kernel<<<(EE + TB - 1) / TB, TB>>>(edges, eattr);
    rsqrt_kernel<<<(NN + TB - 1) / TB, TB>>>();
    scan_kernel<<<1, 1024>>>();
    fill_kernel<<<(EE + TB - 1) / TB, TB>>>(edges, eattr);
    cvt_node_kernel<<<(NN * FF + TB - 1) / TB, TB>>>(node);

    dim3 ggrid(2, (NN + 127) / 128);

    // layer 1: aggregate (bf16 gather over F=128), then GEMM (+bf16 mirror)
    spmm_h_kernel<FF / 2><<<NN, FF / 2>>>(1);
    gemm_bias_kernel<<<ggrid, 256>>>(1, W1, b1, 0, NN, FF, 1);

    // i=0
    spmm_h_kernel<HH / 2><<<NN, HH / 2>>>(1);
    gemm_bias_kernel<<<ggrid, 256>>>(1, Wc + 0 * HH * HH, bc + 0 * HH, 2, NN, HH, 0);
    ln_relu_kernel<<<NN, HH>>>(2, 0, lng + 0 * HH, lnb + 0 * HH, 1);

    // i=1
    spmm_h_kernel<HH / 2><<<NN, HH / 2>>>(0);
    gemm_bias_kernel<<<ggrid, 256>>>(0, Wc + 1 * HH * HH, bc + 1 * HH, 2, NN, HH, 0);
    ln_relu_kernel<<<NN, HH>>>(2, 1, lng + 1 * HH, lnb + 1 * HH, 0);

    // i=2
    spmm_h_kernel<HH / 2><<<NN, HH / 2>>>(1);
    gemm_bias_kernel<<<ggrid, 256>>>(1, Wc + 2 * HH * HH, bc + 2 * HH, 2, NN, HH, 0);
    ln_relu_kernel<<<NN, HH>>>(2, 0, lng + 2 * HH, lnb + 2 * HH, 1);

    pool_kernel<<<256, 256>>>(1, fcW);
    finish_kernel<<<1, 32>>>(fcb, out);
}

// round 11
// speedup vs baseline: 1.6456x; 1.4337x over previous
#include <cuda_runtime.h>
#include <cuda_fp16.h>
#include <mma.h>
#include <cstdint>

using namespace nvcuda;

#define NN 50000
#define NP 50048            // NN padded to multiple of 128 (wmma store, no predication)
#define EE 1600000
#define FF 128
#define HH 256

// ---------------- static device scratch (allocation-free rule) ----------------
__device__ __align__(16) float  g_bufA[(size_t)NP * HH];   // fp32 activations x
__device__ __align__(16) float  g_bufC[(size_t)NP * HH];   // fp32 gemm output
__device__ __align__(16) __half g_h[(size_t)NN * HH];      // fp16 mirror of x (gather src)
__device__ __align__(16) __half g_ha[(size_t)NP * HH];     // fp16 aggregated Sx (gemm A)
__device__ __align__(16) __half g_w16[3 * HH * HH + FF * HH]; // fp16 weights
__device__ float g_dinv[NN];
__device__ int   g_cnt[NN];
__device__ int   g_fill[NN];
__device__ int   g_rowptr[NN + 1];
__device__ int   g_col[EE];
__device__ float g_val[EE];
__device__ float g_acc[2];
__device__ int   g_not64;

__device__ __forceinline__ float* BUF(int s) { return s == 0 ? g_bufA : g_bufC; }

__device__ __forceinline__ int edge_at(const void* edges, size_t idx) {
    if (g_not64) return ((const int*)edges)[idx];
    long long v = ((const long long*)edges)[idx];
    return (int)v;
}

// ---------------- setup kernels ----------------------------------------------
__global__ __launch_bounds__(256) void init_kernel() {
    int i = blockIdx.x * blockDim.x + threadIdx.x;
    if (i < NN) { g_dinv[i] = 1.0f; g_cnt[i] = 0; g_fill[i] = 0; }
    if (i == 0) { g_acc[0] = 0.f; g_acc[1] = 0.f; g_not64 = 0; }
}

__global__ __launch_bounds__(256) void detect_kernel(const void* edges) {
    int i = blockIdx.x * blockDim.x + threadIdx.x;
    if (i >= EE) return;
    long long v = ((const long long*)edges)[i];
    if (v < 0 || v >= NN) atomicOr(&g_not64, 1);
}

__global__ __launch_bounds__(256) void edge_count_kernel(
    const void* __restrict__ edges, const float* __restrict__ w) {
    int e = blockIdx.x * blockDim.x + threadIdx.x;
    if (e >= EE) return;
    int dst = edge_at(edges, (size_t)EE + e);
    if ((unsigned)dst >= NN) return;
    atomicAdd(&g_dinv[dst], w[e]);
    atomicAdd(&g_cnt[dst], 1);
}

__global__ __launch_bounds__(256) void rsqrt_kernel() {
    int i = blockIdx.x * blockDim.x + threadIdx.x;
    if (i < NN) g_dinv[i] = rsqrtf(g_dinv[i]);
}

__global__ __launch_bounds__(1024) void scan_kernel() {
    __shared__ int sh[1024];
    const int CH = (NN + 1023) / 1024;
    int t = threadIdx.x;
    int base = t * CH;
    int s = 0;
    for (int i = 0; i < CH; i++) {
        int idx = base + i;
        if (idx < NN) s += g_cnt[idx];
    }
    sh[t] = s;
    __syncthreads();
    for (int off = 1; off < 1024; off <<= 1) {
        int v = sh[t];
        int add = (t >= off) ? sh[t - off] : 0;
        __syncthreads();
        sh[t] = v + add;
        __syncthreads();
    }
    int run = (t == 0) ? 0 : sh[t - 1];
    for (int i = 0; i < CH; i++) {
        int idx = base + i;
        if (idx < NN) { g_rowptr[idx] = run; run += g_cnt[idx]; }
    }
    if (t == 1023) g_rowptr[NN] = run;
}

__global__ __launch_bounds__(256) void fill_kernel(
    const void* __restrict__ edges, const float* __restrict__ w) {
    int e = blockIdx.x * blockDim.x + threadIdx.x;
    if (e >= EE) return;
    int src = edge_at(edges, e);
    int dst = edge_at(edges, (size_t)EE + e);
    if ((unsigned)src >= NN || (unsigned)dst >= NN) return;
    int pos = g_rowptr[dst] + atomicAdd(&g_fill[dst], 1);
    if ((unsigned)pos >= EE) return;
    g_col[pos] = src;
    g_val[pos] = g_dinv[src] * w[e] * g_dinv[dst];
}

// node features fp32 -> fp16 mirror
__global__ __launch_bounds__(256) void cvt_node_kernel(const float* __restrict__ node) {
    int i = blockIdx.x * blockDim.x + threadIdx.x;
    if (i < NN * FF) g_h[i] = __float2half(node[i]);
}

// weights fp32 -> fp16 (W1 then Wc[3])
__global__ __launch_bounds__(256) void cvt_w_kernel(const float* __restrict__ W1,
                                                    const float* __restrict__ Wc) {
    int i = blockIdx.x * blockDim.x + threadIdx.x;
    const int NW1 = FF * HH, NWC = 3 * HH * HH;
    if (i < NW1) g_w16[i] = __float2half(W1[i]);
    else if (i < NW1 + NWC) g_w16[i] = __float2half(Wc[i - NW1]);
}

// ---------------- SpMM: g_ha = S * g_h (fp16 gather, fp32 accum, fp16 out) ---
// P = feature pairs per row (C/2). One block per node, P threads.
template <int P>
__global__ __launch_bounds__(P) void spmm_h_kernel() {
    const __half2* __restrict__ x = (const __half2*)g_h;
    __half2* __restrict__ y = (__half2*)g_ha;
    int n = blockIdx.x;
    int f = threadIdx.x;
    int s = g_rowptr[n], e = g_rowptr[n + 1];
    float d = g_dinv[n];
    float2 xs = __half22float2(x[(size_t)n * P + f]);
    float ax0 = d * d * xs.x, ay0 = d * d * xs.y;   // self-loop term
    float ax1 = 0.f, ay1 = 0.f, ax2 = 0.f, ay2 = 0.f, ax3 = 0.f, ay3 = 0.f;
    __shared__ int   scol[P];
    __shared__ float sval[P];
    for (int base = s; base < e; base += P) {
        int m = min(P, e - base);
        __syncthreads();
        if (f < m) {
            scol[f] = g_col[base + f];
            sval[f] = g_val[base + f];
        }
        __syncthreads();
        int j = 0;
        for (; j + 4 <= m; j += 4) {
            float2 v0 = __half22float2(x[(size_t)scol[j + 0] * P + f]);
            float2 v1 = __half22float2(x[(size_t)scol[j + 1] * P + f]);
            float2 v2 = __half22float2(x[(size_t)scol[j + 2] * P + f]);
            float2 v3 = __half22float2(x[(size_t)scol[j + 3] * P + f]);
            ax0 = fmaf(sval[j + 0], v0.x, ax0); ay0 = fmaf(sval[j + 0], v0.y, ay0);
            ax1 = fmaf(sval[j + 1], v1.x, ax1); ay1 = fmaf(sval[j + 1], v1.y, ay1);
            ax2 = fmaf(sval[j + 2], v2.x, ax2); ay2 = fmaf(sval[j + 2], v2.y, ay2);
            ax3 = fmaf(sval[j + 3], v3.x, ax3); ay3 = fmaf(sval[j + 3], v3.y, ay3);
        }
        for (; j < m; j++) {
            float2 v = __half22float2(x[(size_t)scol[j] * P + f]);
            ax0 = fmaf(sval[j], v.x, ax0); ay0 = fmaf(sval[j], v.y, ay0);
        }
    }
    y[(size_t)n * P + f] =
        __floats2half2_rn((ax0 + ax1) + (ax2 + ax3), (ay0 + ay1) + (ay2 + ay3));
}

// ---------------- GEMM: C[NP,256] = g_ha[NP,K] @ W16[K,256] (wmma, fp32 acc) -
// block tile 128x128, 8 warps (4x2), each warp 32x64 = 2x4 wmma frags, BK=16.
__global__ __launch_bounds__(256) void gemm_wmma_kernel(int K, int woff, int out_sel) {
    float* __restrict__ C = BUF(out_sel);
    const __half* __restrict__ A  = g_ha;
    const __half* __restrict__ Bh = g_w16 + woff;
    __shared__ alignas(16) __half As[128][16 + 8];   // ld = 24
    __shared__ alignas(16) __half Bs[16][128 + 8];   // ld = 136

    int t = threadIdx.x;
    int wid = t >> 5;
    int warp_m = wid & 3;     // 4 warps down -> 32 rows each
    int warp_n = wid >> 2;    // 2 warps across -> 64 cols each
    int row0 = blockIdx.y * 128;
    int col0 = blockIdx.x * 128;

    wmma::fragment<wmma::accumulator, 16, 16, 16, float> acc[2][4];
#pragma unroll
    for (int i = 0; i < 2; i++)
#pragma unroll
        for (int j = 0; j < 4; j++) wmma::fill_fragment(acc[i][j], 0.0f);

    int ar = t >> 1, ac = (t & 1) * 8;       // A: 128 rows x 16 cols, 8 halves/thread
    int br = t >> 4, bc = (t & 15) * 8;      // B: 16 rows x 128 cols
    bool arow_ok = (row0 + ar) < NN;         // rows >= NN are padding

    for (int k0 = 0; k0 < K; k0 += 16) {
        uint4 av = make_uint4(0u, 0u, 0u, 0u);
        if (arow_ok) av = *(const uint4*)(A + (size_t)(row0 + ar) * K + k0 + ac);
        *(uint4*)&As[ar][ac] = av;
        *(uint4*)&Bs[br][bc] = *(const uint4*)(Bh + (size_t)(k0 + br) * HH + col0 + bc);
        __syncthreads();

        wmma::fragment<wmma::matrix_a, 16, 16, 16, __half, wmma::row_major> af[2];
        wmma::fragment<wmma::matrix_b, 16, 16, 16, __half, wmma::row_major> bf[4];
#pragma unroll
        for (int i = 0; i < 2; i++)
            wmma::load_matrix_sync(af[i], &As[warp_m * 32 + i * 16][0], 24);
#pragma unroll
        for (int j = 0; j < 4; j++)
            wmma::load_matrix_sync(bf[j], &Bs[0][warp_n * 64 + j * 16], 136);
#pragma unroll
        for (int i = 0; i < 2; i++)
#pragma unroll
            for (int j = 0; j < 4; j++)
                wmma::mma_sync(acc[i][j], af[i], bf[j], acc[i][j]);
        __syncthreads();
    }

#pragma unroll
    for (int i = 0; i < 2; i++)
#pragma unroll
        for (int j = 0; j < 4; j++) {
            int r = row0 + warp_m * 32 + i * 16;
            int c = col0 + warp_n * 64 + j * 16;
            wmma::store_matrix_sync(&C[(size_t)r * HH + c], acc[i][j], HH,
                                    wmma::mem_row_major);
        }
}

// ---------------- layer-1 epilogue: x = C + b1 (fp32 + fp16 mirror) ----------
__global__ __launch_bounds__(HH) void ep1_kernel(const float* __restrict__ b1) {
    int n = blockIdx.x;
    int f = threadIdx.x;
    size_t idx = (size_t)n * HH + f;
    float v = g_bufC[idx] + b1[f];
    g_bufA[idx] = v;
    g_h[idx] = __float2half(v);
}

// ---------------- fused bias + LayerNorm + residual + ReLU -------------------
// reads g_bufC (+bias), res/out = g_bufA (in place), writes fp16 mirror g_h.
__global__ __launch_bounds__(HH) void ln_relu_kernel(
    const float* __restrict__ bias,
    const float* __restrict__ g, const float* __restrict__ b) {
    int n = blockIdx.x;
    int f = threadIdx.x;
    size_t idx = (size_t)n * HH + f;
    float v = g_bufC[idx] + bias[f];
    float s = v, q = v * v;
#pragma unroll
    for (int o = 16; o; o >>= 1) {
        s += __shfl_down_sync(0xFFFFFFFFu, s, o);
        q += __shfl_down_sync(0xFFFFFFFFu, q, o);
    }
    __shared__ float ss[8], sq[8];
    int w = f >> 5, l = f & 31;
    if (l == 0) { ss[w] = s; sq[w] = q; }
    __syncthreads();
    if (f == 0) {
        float S = 0.f, Q = 0.f;
#pragma unroll
        for (int i = 0; i < 8; i++) { S += ss[i]; Q += sq[i]; }
        ss[0] = S; sq[0] = Q;
    }
    __syncthreads();
    float mu  = ss[0] * (1.0f / HH);
    float var = sq[0] * (1.0f / HH) - mu * mu;
    var = fmaxf(var, 0.f);
    float rs = rsqrtf(var + 1e-5f);
    float y = (v - mu) * rs * g[f] + b[f] + g_bufA[idx];
    y = fmaxf(y, 0.f);
    g_bufA[idx] = y;
    g_h[idx] = __float2half(y);
}

// ---------------- global mean pool of x @ fc_W --------------------------------
__global__ __launch_bounds__(256) void pool_kernel(const float* __restrict__ fcW) {
    const float* __restrict__ x = g_bufA;
    __shared__ float w0s[HH], w1s[HH];
    int t = threadIdx.x;
    w0s[t] = fcW[2 * t];
    w1s[t] = fcW[2 * t + 1];
    __syncthreads();
    int lane = t & 31, warp = t >> 5;
    int gw = blockIdx.x * 8 + warp;
    int nw = gridDim.x * 8;
    float a0 = 0.f, a1 = 0.f;
    for (int n = gw; n < NN; n += nw) {
        size_t base = (size_t)n * HH;
#pragma unroll
        for (int j = 0; j < 8; j++) {
            float v = x[base + lane + 32 * j];
            a0 += v * w0s[lane + 32 * j];
            a1 += v * w1s[lane + 32 * j];
        }
    }
#pragma unroll
    for (int o = 16; o; o >>= 1) {
        a0 += __shfl_down_sync(0xFFFFFFFFu, a0, o);
        a1 += __shfl_down_sync(0xFFFFFFFFu, a1, o);
    }
    if (lane == 0) {
        atomicAdd(&g_acc[0], a0);
        atomicAdd(&g_acc[1], a1);
    }
}

__global__ __launch_bounds__(32) void finish_kernel(const float* __restrict__ fcb,
                                                    float* __restrict__ out) {
    if (threadIdx.x == 0) {
        out[0] = g_acc[0] * (1.0f / NN) + fcb[0];
        out[1] = g_acc[1] * (1.0f / NN) + fcb[1];
    }
}

// ---------------- launch ------------------------------------------------------
extern "C" void kernel_launch(void* const* d_in, const int* in_sizes, int n_in,
                              void* d_out, int out_size) {
    const float* node  = (const float*)d_in[0];
    const void*  edges = d_in[1];
    const float* eattr = (const float*)d_in[2];
    const float* W1    = (const float*)d_in[3];
    const float* b1    = (const float*)d_in[4];
    const float* Wc    = (const float*)d_in[5];
    const float* bc    = (const float*)d_in[6];
    const float* lng   = (const float*)d_in[7];
    const float* lnb   = (const float*)d_in[8];
    const float* fcW   = (const float*)d_in[9];
    const float* fcb   = (const float*)d_in[10];
    float* out = (float*)d_out;

    const int TB = 256;
    const int NW = FF * HH + 3 * HH * HH;
    init_kernel<<<(NN + TB - 1) / TB, TB>>>();
    detect_kernel<<<(EE + TB - 1) / TB, TB>>>(edges);
    edge_count_kernel<<<(EE + TB - 1) / TB, TB>>>(edges, eattr);
    rsqrt_kernel<<<(NN + TB - 1) / TB, TB>>>();
    scan_kernel<<<1, 1024>>>();
    fill_kernel<<<(EE + TB - 1) / TB, TB>>>(edges, eattr);
    cvt_node_kernel<<<(NN * FF + TB - 1) / TB, TB>>>(node);
    cvt_w_kernel<<<(NW + TB - 1) / TB, TB>>>(W1, Wc);

    dim3 ggrid(2, NP / 128);
    const int WOFF1 = 0, WOFFC = FF * HH;

    // layer 1: aggregate (fp16 gather over F=128), tensor GEMM, epilogue
    spmm_h_kernel<FF / 2><<<NN, FF / 2>>>();
    gemm_wmma_kernel<<<ggrid, 256>>>(FF, WOFF1, 1);
    ep1_kernel<<<NN, HH>>>(b1);

    // 3 message-passing layers
    for (int i = 0; i < 3; i++) {
        spmm_h_kernel<HH / 2><<<NN, HH / 2>>>();
        gemm_wmma_kernel<<<ggrid, 256>>>(HH, WOFFC + i * HH * HH, 1);
        ln_relu_kernel<<<NN, HH>>>(bc + i * HH, lng + i * HH, lnb + i * HH);
    }

    pool_kernel<<<256, 256>>>(fcW);
    finish_kernel<<<1, 32>>>(fcb, out);
}

// round 16
// speedup vs baseline: 1.8231x; 1.1079x over previous
#include <cuda_runtime.h>
#include <cuda_fp16.h>
#include <mma.h>
#include <cstdint>

using namespace nvcuda;

#define NN 50000
#define NP 50048            // NN padded to multiple of 64 (gemm tiles)
#define EE 1600000
#define FF 128
#define HH 256

// ---------------- static device scratch (allocation-free rule) ----------------
__device__ __align__(16) float  g_bufA[(size_t)NP * HH];   // fp32 activations x
__device__ __align__(16) __half g_h[(size_t)NN * HH];      // fp16 mirror of x (gather src)
__device__ __align__(16) __half g_ha[(size_t)NP * HH];     // fp16 aggregated Sx (gemm A)
__device__ __align__(16) __half g_w16[3 * HH * HH + FF * HH]; // fp16 weights
__device__ float g_dinv[NN];
__device__ int   g_cnt[NN];
__device__ int   g_fill[NN];
__device__ int   g_rowptr[NN + 1];
__device__ int   g_col[EE];
__device__ float g_val[EE];
__device__ float g_acc[2];
__device__ int   g_not64;

__device__ __forceinline__ int edge_at(const void* edges, size_t idx) {
    if (g_not64) return ((const int*)edges)[idx];
    long long v = ((const long long*)edges)[idx];
    return (int)v;
}

// ---------------- setup kernels ----------------------------------------------
__global__ __launch_bounds__(256) void init_kernel() {
    int i = blockIdx.x * blockDim.x + threadIdx.x;
    if (i < NN) { g_dinv[i] = 1.0f; g_cnt[i] = 0; g_fill[i] = 0; }
    if (i == 0) { g_acc[0] = 0.f; g_acc[1] = 0.f; g_not64 = 0; }
}

__global__ __launch_bounds__(256) void detect_kernel(const void* edges) {
    int i = blockIdx.x * blockDim.x + threadIdx.x;
    if (i >= EE) return;
    long long v = ((const long long*)edges)[i];
    if (v < 0 || v >= NN) atomicOr(&g_not64, 1);
}

__global__ __launch_bounds__(256) void edge_count_kernel(
    const void* __restrict__ edges, const float* __restrict__ w) {
    int e = blockIdx.x * blockDim.x + threadIdx.x;
    if (e >= EE) return;
    int dst = edge_at(edges, (size_t)EE + e);
    if ((unsigned)dst >= NN) return;
    atomicAdd(&g_dinv[dst], w[e]);
    atomicAdd(&g_cnt[dst], 1);
}

// scan over g_cnt -> g_rowptr; also converts g_dinv (deg) -> rsqrt(deg) in pass 1
__global__ __launch_bounds__(1024) void scan_kernel() {
    __shared__ int sh[1024];
    const int CH = (NN + 1023) / 1024;
    int t = threadIdx.x;
    int base = t * CH;
    int s = 0;
    for (int i = 0; i < CH; i++) {
        int idx = base + i;
        if (idx < NN) {
            s += g_cnt[idx];
            g_dinv[idx] = rsqrtf(g_dinv[idx]);   // deg >= 1 always (self loop)
        }
    }
    sh[t] = s;
    __syncthreads();
    for (int off = 1; off < 1024; off <<= 1) {
        int v = sh[t];
        int add = (t >= off) ? sh[t - off] : 0;
        __syncthreads();
        sh[t] = v + add;
        __syncthreads();
    }
    int run = (t == 0) ? 0 : sh[t - 1];
    for (int i = 0; i < CH; i++) {
        int idx = base + i;
        if (idx < NN) { g_rowptr[idx] = run; run += g_cnt[idx]; }
    }
    if (t == 1023) g_rowptr[NN] = run;
}

__global__ __launch_bounds__(256) void fill_kernel(
    const void* __restrict__ edges, const float* __restrict__ w) {
    int e = blockIdx.x * blockDim.x + threadIdx.x;
    if (e >= EE) return;
    int src = edge_at(edges, e);
    int dst = edge_at(edges, (size_t)EE + e);
    if ((unsigned)src >= NN || (unsigned)dst >= NN) return;
    int pos = g_rowptr[dst] + atomicAdd(&g_fill[dst], 1);
    if ((unsigned)pos >= EE) return;
    g_col[pos] = src;
    g_val[pos] = g_dinv[src] * w[e] * g_dinv[dst];
}

__global__ __launch_bounds__(256) void cvt_node_kernel(const float* __restrict__ node) {
    int i = blockIdx.x * blockDim.x + threadIdx.x;
    if (i < NN * FF) g_h[i] = __float2half(node[i]);
}

__global__ __launch_bounds__(256) void cvt_w_kernel(const float* __restrict__ W1,
                                                    const float* __restrict__ Wc) {
    int i = blockIdx.x * blockDim.x + threadIdx.x;
    const int NW1 = FF * HH, NWC = 3 * HH * HH;
    if (i < NW1) g_w16[i] = __float2half(W1[i]);
    else if (i < NW1 + NWC) g_w16[i] = __float2half(Wc[i - NW1]);
}

// ---------------- SpMM: g_ha = S * g_h (fp16 gather, fp32 accum, fp16 out) ---
template <int P>
__global__ __launch_bounds__(P) void spmm_h_kernel() {
    const __half2* __restrict__ x = (const __half2*)g_h;
    __half2* __restrict__ y = (__half2*)g_ha;
    int n = blockIdx.x;
    int f = threadIdx.x;
    int s = g_rowptr[n], e = g_rowptr[n + 1];
    float d = g_dinv[n];
    float2 xs = __half22float2(x[(size_t)n * P + f]);
    float ax0 = d * d * xs.x, ay0 = d * d * xs.y;   // self-loop term
    float ax1 = 0.f, ay1 = 0.f, ax2 = 0.f, ay2 = 0.f, ax3 = 0.f, ay3 = 0.f;
    __shared__ int   scol[P];
    __shared__ float sval[P];
    for (int base = s; base < e; base += P) {
        int m = min(P, e - base);
        __syncthreads();
        if (f < m) {
            scol[f] = g_col[base + f];
            sval[f] = g_val[base + f];
        }
        __syncthreads();
        int j = 0;
        for (; j + 4 <= m; j += 4) {
            float2 v0 = __half22float2(x[(size_t)scol[j + 0] * P + f]);
            float2 v1 = __half22float2(x[(size_t)scol[j + 1] * P + f]);
            float2 v2 = __half22float2(x[(size_t)scol[j + 2] * P + f]);
            float2 v3 = __half22float2(x[(size_t)scol[j + 3] * P + f]);
            ax0 = fmaf(sval[j + 0], v0.x, ax0); ay0 = fmaf(sval[j + 0], v0.y, ay0);
            ax1 = fmaf(sval[j + 1], v1.x, ax1); ay1 = fmaf(sval[j + 1], v1.y, ay1);
            ax2 = fmaf(sval[j + 2], v2.x, ax2); ay2 = fmaf(sval[j + 2], v2.y, ay2);
            ax3 = fmaf(sval[j + 3], v3.x, ax3); ay3 = fmaf(sval[j + 3], v3.y, ay3);
        }
        for (; j < m; j++) {
            float2 v = __half22float2(x[(size_t)scol[j] * P + f]);
            ax0 = fmaf(sval[j], v.x, ax0); ay0 = fmaf(sval[j], v.y, ay0);
        }
    }
    y[(size_t)n * P + f] =
        __floats2half2_rn((ax0 + ax1) + (ax2 + ax3), (ay0 + ay1) + (ay2 + ay3));
}

// ---------------- fused GEMM + bias (+LN+residual+ReLU) + fp16 mirror --------
// tile 64x256, 8 warps (2 warp_m x 4 warp_n), warp 32x64, BK=32.
// mode 0: x = A@W + bias            (layer 1)
// mode 1: x = relu(LN(A@W + bias) + x)   (conv layers; residual = g_bufA in)
// Accumulator tiles staged through smem (reusing As/Bs space) for row-wise LN.
__global__ __launch_bounds__(256) void gemm_ln_kernel(
    int K, int woff, const float* __restrict__ bias,
    const float* __restrict__ gamma, const float* __restrict__ beta, int mode) {
    const __half* __restrict__ A  = g_ha;
    const __half* __restrict__ Bh = g_w16 + woff;
    __shared__ alignas(16) unsigned char sm[36864];
    __half (*As)[40]  = (__half(*)[40])sm;              // 64 x 40 halves (5120 B)
    __half (*Bs)[264] = (__half(*)[264])(sm + 5120);    // 32 x 264 halves (16896 B)
    float (*S)[264]   = (float(*)[264])sm;              // 32 x 264 fp32 (reuse, 33792 B)
    float* pb = (float*)(sm + 33792);                   // bias[256]
    float* pg = pb + 256;                               // gamma[256] (3072 B total)
    float* pp = pg + 256;                               // beta[256]

    int t = threadIdx.x;
    pb[t] = bias[t]; pg[t] = gamma[t]; pp[t] = beta[t];

    int wid = t >> 5;
    int warp_m = wid & 1;        // 2 groups of 32 rows
    int warp_n = wid >> 1;       // 4 groups of 64 cols
    int row0 = blockIdx.x * 64;

    wmma::fragment<wmma::accumulator, 16, 16, 16, float> acc[2][4];
#pragma unroll
    for (int i = 0; i < 2; i++)
#pragma unroll
        for (int j = 0; j < 4; j++) wmma::fill_fragment(acc[i][j], 0.0f);

    int ar = t >> 2, ac = (t & 3) * 8;       // A: 64 rows x 32 halves
    int br = t >> 5, bc = (t & 31) * 8;      // B: 8 rows/pass x 256 cols, 4 passes
    bool aok = (row0 + ar) < NN;

    for (int k0 = 0; k0 < K; k0 += 32) {
        uint4 av = make_uint4(0u, 0u, 0u, 0u);
        if (aok) av = *(const uint4*)(A + (size_t)(row0 + ar) * K + k0 + ac);
        *(uint4*)&As[ar][ac] = av;
#pragma unroll
        for (int it = 0; it < 4; it++)
            *(uint4*)&Bs[br + 8 * it][bc] =
                *(const uint4*)(Bh + (size_t)(k0 + br + 8 * it) * HH + bc);
        __syncthreads();
#pragma unroll
        for (int ks = 0; ks < 2; ks++) {
            wmma::fragment<wmma::matrix_a, 16, 16, 16, __half, wmma::row_major> af[2];
            wmma::fragment<wmma::matrix_b, 16, 16, 16, __half, wmma::row_major> bf[4];
#pragma unroll
            for (int i = 0; i < 2; i++)
                wmma::load_matrix_sync(af[i], &As[warp_m * 32 + i * 16][ks * 16], 40);
#pragma unroll
            for (int j = 0; j < 4; j++)
                wmma::load_matrix_sync(bf[j], &Bs[ks * 16][warp_n * 64 + j * 16], 264);
#pragma unroll
            for (int i = 0; i < 2; i++)
#pragma unroll
                for (int j = 0; j < 4; j++)
                    wmma::mma_sync(acc[i][j], af[i], bf[j], acc[i][j]);
        }
        __syncthreads();
    }

    // epilogue: two passes of 32 rows through S
#pragma unroll
    for (int p = 0; p < 2; p++) {
        if (warp_m == p) {
#pragma unroll
            for (int i = 0; i < 2; i++)
#pragma unroll
                for (int j = 0; j < 4; j++)
                    wmma::store_matrix_sync(&S[i * 16][warp_n * 64 + j * 16],
                                            acc[i][j], 264, wmma::mem_row_major);
        }
        __syncthreads();

        int lrow = t >> 3;           // 0..31
        int lane8 = t & 7;
        int grow = row0 + p * 32 + lrow;

        float4 v[8];
        float sum = 0.f, sq = 0.f;
#pragma unroll
        for (int i = 0; i < 8; i++) {
            int c = lane8 * 4 + i * 32;
            v[i] = *(float4*)&S[lrow][c];
            v[i].x += pb[c + 0]; v[i].y += pb[c + 1];
            v[i].z += pb[c + 2]; v[i].w += pb[c + 3];
            sum += (v[i].x + v[i].y) + (v[i].z + v[i].w);
            sq  += (v[i].x * v[i].x + v[i].y * v[i].y) +
                   (v[i].z * v[i].z + v[i].w * v[i].w);
        }
        if (mode) {
#pragma unroll
            for (int o = 4; o; o >>= 1) {
                sum += __shfl_down_sync(0xFFFFFFFFu, sum, o, 8);
                sq  += __shfl_down_sync(0xFFFFFFFFu, sq, o, 8);
            }
            sum = __shfl_sync(0xFFFFFFFFu, sum, 0, 8);
            sq  = __shfl_sync(0xFFFFFFFFu, sq, 0, 8);
            float mu  = sum * (1.0f / HH);
            float var = sq * (1.0f / HH) - mu * mu;
            var = fmaxf(var, 0.f);
            float rs = rsqrtf(var + 1e-5f);
            if (grow < NN) {
#pragma unroll
                for (int i = 0; i < 8; i++) {
                    int c = lane8 * 4 + i * 32;
                    float4 r = *(float4*)&g_bufA[(size_t)grow * HH + c];
                    float4 o;
                    o.x = fmaxf((v[i].x - mu) * rs * pg[c + 0] + pp[c + 0] + r.x, 0.f);
                    o.y = fmaxf((v[i].y - mu) * rs * pg[c + 1] + pp[c + 1] + r.y, 0.f);
                    o.z = fmaxf((v[i].z - mu) * rs * pg[c + 2] + pp[c + 2] + r.z, 0.f);
                    o.w = fmaxf((v[i].w - mu) * rs * pg[c + 3] + pp[c + 3] + r.w, 0.f);
                    *(float4*)&g_bufA[(size_t)grow * HH + c] = o;
                    __half2* hp = (__half2*)(g_h + (size_t)grow * HH + c);
                    hp[0] = __floats2half2_rn(o.x, o.y);
                    hp[1] = __floats2half2_rn(o.z, o.w);
                }
            }
        } else if (grow < NN) {
#pragma unroll
            for (int i = 0; i < 8; i++) {
                int c = lane8 * 4 + i * 32;
                *(float4*)&g_bufA[(size_t)grow * HH + c] = v[i];
                __half2* hp = (__half2*)(g_h + (size_t)grow * HH + c);
                hp[0] = __floats2half2_rn(v[i].x, v[i].y);
                hp[1] = __floats2half2_rn(v[i].z, v[i].w);
            }
        }
        __syncthreads();
    }
}

// ---------------- global mean pool of x @ fc_W --------------------------------
__global__ __launch_bounds__(256) void pool_kernel(const float* __restrict__ fcW) {
    const float* __restrict__ x = g_bufA;
    __shared__ float w0s[HH], w1s[HH];
    int t = threadIdx.x;
    w0s[t] = fcW[2 * t];
    w1s[t] = fcW[2 * t + 1];
    __syncthreads();
    int lane = t & 31, warp = t >> 5;
    int gw = blockIdx.x * 8 + warp;
    int nw = gridDim.x * 8;
    float a0 = 0.f, a1 = 0.f;
    for (int n = gw; n < NN; n += nw) {
        size_t base = (size_t)n * HH;
#pragma unroll
        for (int j = 0; j < 8; j++) {
            float v = x[base + lane + 32 * j];
            a0 += v * w0s[lane + 32 * j];
            a1 += v * w1s[lane + 32 * j];
        }
    }
#pragma unroll
    for (int o = 16; o; o >>= 1) {
        a0 += __shfl_down_sync(0xFFFFFFFFu, a0, o);
        a1 += __shfl_down_sync(0xFFFFFFFFu, a1, o);
    }
    if (lane == 0) {
        atomicAdd(&g_acc[0], a0);
        atomicAdd(&g_acc[1], a1);
    }
}

__global__ __launch_bounds__(32) void finish_kernel(const float* __restrict__ fcb,
                                                    float* __restrict__ out) {
    if (threadIdx.x == 0) {
        out[0] = g_acc[0] * (1.0f / NN) + fcb[0];
        out[1] = g_acc[1] * (1.0f / NN) + fcb[1];
    }
}

// ---------------- launch ------------------------------------------------------
extern "C" void kernel_launch(void* const* d_in, const int* in_sizes, int n_in,
                              void* d_out, int out_size) {
    const float* node  = (const float*)d_in[0];
    const void*  edges = d_in[1];
    const float* eattr = (const float*)d_in[2];
    const float* W1    = (const float*)d_in[3];
    const float* b1    = (const float*)d_in[4];
    const float* Wc    = (const float*)d_in[5];
    const float* bc    = (const float*)d_in[6];
    const float* lng   = (const float*)d_in[7];
    const float* lnb   = (const float*)d_in[8];
    const float* fcW   = (const float*)d_in[9];
    const float* fcb   = (const float*)d_in[10];
    float* out = (float*)d_out;

    const int TB = 256;
    const int NW = FF * HH + 3 * HH * HH;
    init_kernel<<<(NN + TB - 1) / TB, TB>>>();
    detect_kernel<<<(EE + TB - 1) / TB, TB>>>(edges);
    edge_count_kernel<<<(EE + TB - 1) / TB, TB>>>(edges, eattr);
    scan_kernel<<<1, 1024>>>();
    fill_kernel<<<(EE + TB - 1) / TB, TB>>>(edges, eattr);
    cvt_node_kernel<<<(NN * FF + TB - 1) / TB, TB>>>(node);
    cvt_w_kernel<<<(NW + TB - 1) / TB, TB>>>(W1, Wc);

    const int GG = NP / 64;       // 782 blocks
    const int WOFFC = FF * HH;

    // layer 1: aggregate (fp16 gather, F=128), fused GEMM+bias
    spmm_h_kernel<FF / 2><<<NN, FF / 2>>>();
    gemm_ln_kernel<<<GG, 256>>>(FF, 0, b1, b1, b1, 0);

    // 3 message-passing layers: fused GEMM+bias+LN+residual+ReLU
    for (int i = 0; i < 3; i++) {
        spmm_h_kernel<HH / 2><<<NN, HH / 2>>>();
        gemm_ln_kernel<<<GG, 256>>>(HH, WOFFC + i * HH * HH, bc + i * HH,
                                    lng + i * HH, lnb + i * HH, 1);
    }

    pool_kernel<<<256, 256>>>(fcW);
    finish_kernel<<<1, 32>>>(fcb, out);
}